// round 5
// baseline (speedup 1.0000x reference)
#include <cuda_runtime.h>
#include <cuda_bf16.h>
#include <math.h>
#include <stdint.h>

#define D     128
#define MAXN  8192
#define BM    128
#define PW    132            // p-tile smem pitch (floats)

// smem byte offsets
#define SA_OFF   0
#define SB_OFF   67584       // 128*132*4
#define RG_OFF   135168      // pair regions: 16 warps * 16 slots * 32 * u32
#define RC_OFF   167936      // rowcnt: 256 * int
#define SQI_OFF  168960
#define SQJ_OFF  169472
#define SMEM_TOT 169984

__device__ float g_p[(size_t)MAXN * D];
__device__ float g_sq[MAXN];
__device__ float g_negdist[MAXN];
__device__ float g_possum[MAXN];
__device__ float g_cnt[MAXN];

__device__ __forceinline__ uint32_t smem_u32(const void* p) {
    uint32_t a;
    asm("{ .reg .u64 t; cvta.to.shared.u64 t, %1; cvt.u32.u64 %0, t; }"
        : "=r"(a) : "l"(p));
    return a;
}
__device__ __forceinline__ void cp_async16(uint32_t dst, const void* src) {
    size_t g = __cvta_generic_to_global(src);
    asm volatile("cp.async.cg.shared.global [%0], [%1], 16;"
                 :: "r"(dst), "l"(g) : "memory");
}

// ---------------------------------------------------------------------------
// Kernel 1: warp-per-row normalize; emits g_p (fp32), g_sq, g_negdist,
// zeroes accumulators (graph-replay safe).
// ---------------------------------------------------------------------------
__global__ __launch_bounds__(256) void k_normalize(const float* __restrict__ pred,
                                                   const float* __restrict__ neg,
                                                   int N) {
    int w = threadIdx.x >> 5, lane = threadIdx.x & 31;
    int row = blockIdx.x * 8 + w;
    const float4* p4 = (const float4*)pred + (size_t)row * 32;
    const float4* n4 = (const float4*)neg + (size_t)row * 32;
    float4 pv = p4[lane];
    float4 nv = n4[lane];
    float s1 = pv.x * pv.x + pv.y * pv.y + pv.z * pv.z + pv.w * pv.w;
    float s2 = nv.x * nv.x + nv.y * nv.y + nv.z * nv.z + nv.w * nv.w;
    #pragma unroll
    for (int o = 16; o > 0; o >>= 1) {
        s1 += __shfl_xor_sync(0xffffffffu, s1, o);
        s2 += __shfl_xor_sync(0xffffffffu, s2, o);
    }
    float r1 = fmaxf(sqrtf(s1), 1e-12f);
    float r2 = fmaxf(sqrtf(s2), 1e-12f);
    float4 pn = make_float4(pv.x / r1, pv.y / r1, pv.z / r1, pv.w / r1);
    float4 nn = make_float4(nv.x / r2, nv.y / r2, nv.z / r2, nv.w / r2);
    float s3 = pn.x * pn.x + pn.y * pn.y + pn.z * pn.z + pn.w * pn.w;
    float dx = pn.x - nn.x, dy = pn.y - nn.y, dz = pn.z - nn.z, dw = pn.w - nn.w;
    float s4 = dx * dx + dy * dy + dz * dz + dw * dw;
    #pragma unroll
    for (int o = 16; o > 0; o >>= 1) {
        s3 += __shfl_xor_sync(0xffffffffu, s3, o);
        s4 += __shfl_xor_sync(0xffffffffu, s4, o);
    }
    ((float4*)g_p)[(size_t)row * 32 + lane] = pn;
    if (lane == 0) {
        g_sq[row]      = s3;
        g_negdist[row] = (s4 > 0.f) ? sqrtf(s4) : 0.f;
        g_possum[row]  = 0.f;
        g_cnt[row]     = 0.f;
    }
}

// ---------------------------------------------------------------------------
// Kernel 2: sparse masked distances. One CTA per upper-triangular 128x128
// tile. Stage p tiles via cp.async (overlapped with DRAM mask read), emit
// per-warp per-row pair lists from the mask, then compute only the ~9.75%
// of distances actually used. Exact fp32 throughout.
// ---------------------------------------------------------------------------
__global__ __launch_bounds__(512) void k_sparse(const float* __restrict__ mask,
                                                int N, int nb) {
    // triangular decode
    int t = blockIdx.x;
    float ff = (float)(2 * nb + 1);
    int bi = (int)((ff - sqrtf(ff * ff - 8.0f * (float)t)) * 0.5f);
    #pragma unroll 1
    while (bi > 0 && (bi * nb - (bi * (bi - 1)) / 2) > t) bi--;
    #pragma unroll 1
    while (((bi + 1) * nb - ((bi + 1) * bi) / 2) <= t) bi++;
    int bj = bi + (t - (bi * nb - (bi * (bi - 1)) / 2));
    bool diag = (bi == bj);
    int I = bi * BM, J = bj * BM;

    extern __shared__ char sm[];
    float*    A  = (float*)(sm + SA_OFF);
    float*    B  = (float*)(sm + SB_OFF);
    uint32_t* RG = (uint32_t*)(sm + RG_OFF);
    int*      RC = (int*)(sm + RC_OFF);
    float*    sqI = (float*)(sm + SQI_OFF);
    float*    sqJ = (float*)(sm + SQJ_OFF);
    uint32_t sbase = smem_u32(sm);

    int tid = threadIdx.x, w = tid >> 5, lane = tid & 31;

    // ---- stage p tiles (cp.async), sq rows, zero rowcnt ----
    #pragma unroll
    for (int c = tid; c < 4096; c += 512) {
        int r = c >> 5, f = c & 31;
        cp_async16(sbase + SA_OFF + (uint32_t)(r * (PW * 4) + f * 16),
                   g_p + (size_t)(I + r) * D + f * 4);
        cp_async16(sbase + SB_OFF + (uint32_t)(r * (PW * 4) + f * 16),
                   g_p + (size_t)(J + r) * D + f * 4);
    }
    asm volatile("cp.async.commit_group;" ::: "memory");
    if (tid < 128) sqI[tid] = g_sq[I + tid];
    else if (tid < 256) sqJ[tid - 128] = g_sq[J + tid - 128];
    else if (tid < 512 && (tid - 256) < 256) RC[tid - 256] = 0;
    __syncthreads();

    // ---- mask phase: counts + pair emission (per-warp private regions) ----
    // side A: rows I + w*8 + s, cols J.. ; side B: rows J + w*8 + s, cols I..
    {
        float4 mA[8], mB[8];
        #pragma unroll
        for (int s = 0; s < 8; s++) {
            int grow = I + w * 8 + s;
            mA[s] = *((const float4*)(mask + (size_t)grow * N + J) + lane);
        }
        if (!diag) {
            #pragma unroll
            for (int s = 0; s < 8; s++) {
                int grow = J + w * 8 + s;
                mB[s] = *((const float4*)(mask + (size_t)grow * N + I) + lane);
            }
        }
        #pragma unroll
        for (int side = 0; side < 2; side++) {
            if (side == 1 && diag) break;
            #pragma unroll
            for (int s = 0; s < 8; s++) {
                float4 m = (side == 0) ? mA[s] : mB[s];
                int slot = w * 16 + side * 8 + s;
                int nz0 = (m.x != 0.f), nz1 = (m.y != 0.f),
                    nz2 = (m.z != 0.f), nz3 = (m.w != 0.f);
                int k = nz0 + nz1 + nz2 + nz3;
                int incl = k;
                #pragma unroll
                for (int o = 1; o < 32; o <<= 1) {
                    int v = __shfl_up_sync(0xffffffffu, incl, o);
                    if (lane >= o) incl += v;
                }
                int off = incl - k;
                uint32_t* reg = RG + slot * 32;
                int cb = lane * 4;
                if (nz0 && off < 32) reg[off] = cb + 0; off += nz0;
                if (nz1 && off < 32) reg[off] = cb + 1; off += nz1;
                if (nz2 && off < 32) reg[off] = cb + 2; off += nz2;
                if (nz3 && off < 32) reg[off] = cb + 3; off += nz3;
                int total = __shfl_sync(0xffffffffu, incl, 31);
                if (lane == 0) {
                    RC[slot] = (total < 32) ? total : 32;
                    int grow = (side == 0) ? (I + w * 8 + s) : (J + w * 8 + s);
                    atomicAdd(&g_cnt[grow], (float)total);
                }
            }
        }
    }
    asm volatile("cp.async.wait_group 0;" ::: "memory");
    __syncthreads();

    // ---- compute phase: 4 pairs per group, 8 lanes per pair ----
    int p = lane & 3, q = lane >> 2;
    #pragma unroll 1
    for (int s = 0; s < 16; s++) {
        int slot = w * 16 + s;
        int cnt = RC[slot];
        if (cnt == 0) continue;
        int hr = w * 8 + (s & 7);
        bool sideB = (s >= 8);
        const float* held   = sideB ? B : A;
        const float* stream = sideB ? A : B;
        const float* sqh_t  = sideB ? sqJ : sqI;
        const float* sqs_t  = sideB ? sqI : sqJ;
        int target = (sideB ? J : I) + hr;
        float sqh = sqh_t[hr];

        const float4* hrow = (const float4*)(held + hr * PW + q * 16);
        float4 h0 = hrow[0], h1 = hrow[1], h2 = hrow[2], h3 = hrow[3];

        const uint32_t* reg = RG + slot * 32;
        float row_acc = 0.f;
        #pragma unroll 1
        for (int g = 0; g < cnt; g += 4) {
            int idx = g + p;
            bool valid = idx < cnt;
            int cb = (int)(reg[idx < 31 ? idx : 31] & 127u);
            const float4* brow = (const float4*)(stream + cb * PW + q * 16);
            float4 b0 = brow[0], b1 = brow[1], b2 = brow[2], b3 = brow[3];
            float d0 = h0.x * b0.x, d1 = h2.x * b2.x;
            d0 = fmaf(h0.y, b0.y, d0); d1 = fmaf(h2.y, b2.y, d1);
            d0 = fmaf(h0.z, b0.z, d0); d1 = fmaf(h2.z, b2.z, d1);
            d0 = fmaf(h0.w, b0.w, d0); d1 = fmaf(h2.w, b2.w, d1);
            d0 = fmaf(h1.x, b1.x, d0); d1 = fmaf(h3.x, b3.x, d1);
            d0 = fmaf(h1.y, b1.y, d0); d1 = fmaf(h3.y, b3.y, d1);
            d0 = fmaf(h1.z, b1.z, d0); d1 = fmaf(h3.z, b3.z, d1);
            d0 = fmaf(h1.w, b1.w, d0); d1 = fmaf(h3.w, b3.w, d1);
            float dot = d0 + d1;
            #pragma unroll
            for (int o = 4; o < 32; o <<= 1)
                dot += __shfl_xor_sync(0xffffffffu, dot, o);
            float d2 = sqh + sqs_t[cb] - 2.f * dot;
            float dist = sqrtf(fmaxf(d2, 0.f));
            if (valid && q == 0) row_acc += dist;
        }
        #pragma unroll
        for (int o = 16; o > 0; o >>= 1)
            row_acc += __shfl_xor_sync(0xffffffffu, row_acc, o);
        if (lane == 0) atomicAdd(&g_possum[target], row_acc);
    }
}

// ---------------------------------------------------------------------------
// Kernel 3: final scalar mean
// ---------------------------------------------------------------------------
__global__ void k_final(float* __restrict__ out, int N) {
    __shared__ float sb[32];
    float s = 0.f;
    for (int i = threadIdx.x; i < N; i += blockDim.x)
        s += g_possum[i] / fmaxf(g_cnt[i], 1.f) - g_negdist[i];
    #pragma unroll
    for (int o = 16; o > 0; o >>= 1) s += __shfl_down_sync(0xffffffffu, s, o);
    int lane = threadIdx.x & 31, w = threadIdx.x >> 5;
    if (lane == 0) sb[w] = s;
    __syncthreads();
    if (w == 0) {
        float r = (lane < (int)(blockDim.x >> 5)) ? sb[lane] : 0.f;
        #pragma unroll
        for (int o = 16; o > 0; o >>= 1) r += __shfl_down_sync(0xffffffffu, r, o);
        if (lane == 0) out[0] = r / (float)N;
    }
}

// ---------------------------------------------------------------------------
extern "C" void kernel_launch(void* const* d_in, const int* in_sizes, int n_in,
                              void* d_out, int out_size) {
    const float* pred = (const float*)d_in[0];
    const float* mask = (const float*)d_in[1];
    const float* neg  = (const float*)d_in[2];
    int N = in_sizes[0] / D;

    k_normalize<<<N / 8, 256>>>(pred, neg, N);

    int nb = N / BM;
    int ntiles = nb * (nb + 1) / 2;
    cudaFuncSetAttribute(k_sparse, cudaFuncAttributeMaxDynamicSharedMemorySize,
                         SMEM_TOT);
    k_sparse<<<ntiles, 512, SMEM_TOT>>>(mask, N, nb);

    k_final<<<1, 1024>>>((float*)d_out, N);
}

// round 6
// speedup vs baseline: 1.4697x; 1.4697x over previous
#include <cuda_runtime.h>
#include <cuda_fp16.h>
#include <math.h>
#include <stdint.h>

#define D      128
#define MAXN   8192
#define BM     128
#define PITCHB 272              // smem tile pitch bytes (136 halves)
#define TILEB  (128 * PITCHB)   // 34816
#define PT     129              // dist tile pitch (floats)
#define PACK   16777216.0       // 2^24 for (ps, ct) double packing

__device__ __half  g_h[(size_t)MAXN * D];
__device__ float   g_sqh[MAXN];
__device__ float   g_negdist[MAXN];
__device__ double  g_acc[MAXN];

// ---------------- helpers ----------------
__device__ __forceinline__ uint32_t smem_u32(const void* p) {
    uint32_t a;
    asm("{ .reg .u64 t; cvta.to.shared.u64 t, %1; cvt.u32.u64 %0, t; }"
        : "=r"(a) : "l"(p));
    return a;
}
__device__ __forceinline__ void cp_async16(uint32_t dst, const void* src) {
    size_t g = __cvta_generic_to_global(src);
    asm volatile("cp.async.cg.shared.global [%0], [%1], 16;"
                 :: "r"(dst), "l"(g) : "memory");
}
__device__ __forceinline__ void ldm_x4(uint32_t* r, uint32_t addr) {
    asm volatile("ldmatrix.sync.aligned.m8n8.x4.shared.b16 {%0,%1,%2,%3}, [%4];"
                 : "=r"(r[0]), "=r"(r[1]), "=r"(r[2]), "=r"(r[3]) : "r"(addr));
}
__device__ __forceinline__ void mma_f16(float* c, const uint32_t* a,
                                        uint32_t b0, uint32_t b1) {
    asm volatile(
        "mma.sync.aligned.m16n8k16.row.col.f32.f16.f16.f32 "
        "{%0,%1,%2,%3}, {%4,%5,%6,%7}, {%8,%9}, {%0,%1,%2,%3};"
        : "+f"(c[0]), "+f"(c[1]), "+f"(c[2]), "+f"(c[3])
        : "r"(a[0]), "r"(a[1]), "r"(a[2]), "r"(a[3]), "r"(b0), "r"(b1));
}

// ---------------------------------------------------------------------------
// Kernel 1: warp-per-row normalize; writes fp16 rows, sq of ROUNDED rows
// (so d2 = |p^_i - p^_j|^2 is exact-consistent), exact neg_dist, zero acc.
// ---------------------------------------------------------------------------
__global__ __launch_bounds__(256) void k_normalize(const float* __restrict__ pred,
                                                   const float* __restrict__ neg,
                                                   int N) {
    int w = threadIdx.x >> 5, lane = threadIdx.x & 31;
    int row = blockIdx.x * 8 + w;
    float4 pv = ((const float4*)pred)[(size_t)row * 32 + lane];
    float4 nv = ((const float4*)neg)[(size_t)row * 32 + lane];
    float s1 = pv.x * pv.x + pv.y * pv.y + pv.z * pv.z + pv.w * pv.w;
    float s2 = nv.x * nv.x + nv.y * nv.y + nv.z * nv.z + nv.w * nv.w;
    #pragma unroll
    for (int o = 16; o > 0; o >>= 1) {
        s1 += __shfl_xor_sync(0xffffffffu, s1, o);
        s2 += __shfl_xor_sync(0xffffffffu, s2, o);
    }
    float r1 = fmaxf(sqrtf(s1), 1e-12f);
    float r2 = fmaxf(sqrtf(s2), 1e-12f);
    float4 pn = make_float4(pv.x / r1, pv.y / r1, pv.z / r1, pv.w / r1);
    float4 nn = make_float4(nv.x / r2, nv.y / r2, nv.z / r2, nv.w / r2);

    __half h0 = __float2half(pn.x), h1 = __float2half(pn.y);
    __half h2 = __float2half(pn.z), h3 = __float2half(pn.w);
    float f0 = __half2float(h0), f1 = __half2float(h1);
    float f2 = __half2float(h2), f3 = __half2float(h3);
    float s3 = f0 * f0 + f1 * f1 + f2 * f2 + f3 * f3;   // sq of rounded
    float dx = pn.x - nn.x, dy = pn.y - nn.y, dz = pn.z - nn.z, dw = pn.w - nn.w;
    float s4 = dx * dx + dy * dy + dz * dz + dw * dw;
    #pragma unroll
    for (int o = 16; o > 0; o >>= 1) {
        s3 += __shfl_xor_sync(0xffffffffu, s3, o);
        s4 += __shfl_xor_sync(0xffffffffu, s4, o);
    }
    __half2* dst = (__half2*)(g_h + (size_t)row * D) + lane * 2;
    dst[0] = __halves2half2(h0, h1);
    dst[1] = __halves2half2(h2, h3);
    if (lane == 0) {
        g_sqh[row]     = s3;
        g_negdist[row] = (s4 > 0.f) ? sqrtf(s4) : 0.f;
        g_acc[row]     = 0.0;
    }
}

// ---------------------------------------------------------------------------
// Kernel 2: 128x128 gram tiles (upper triangle), SINGLE fp16 mma pass,
// cp.async staging, fused dist + mask epilogue for both orientations,
// one packed double atomic per row-side.
// ---------------------------------------------------------------------------
#define OFF_SQI (2 * TILEB)
#define OFF_SQJ (2 * TILEB + 512)
#define SMEM_SZ (2 * TILEB + 1024)

__global__ __launch_bounds__(256) void k_gram(const float* __restrict__ mask,
                                              int N) {
    int bi = blockIdx.x, bj = blockIdx.y;
    if (bj < bi) return;
    bool diag = (bi == bj);
    int I = bi * BM, J = bj * BM;

    extern __shared__ char smem[];
    uint32_t sbase = smem_u32(smem);
    float* sdist = (float*)smem;
    float* sqi = (float*)(smem + OFF_SQI);
    float* sqj = (float*)(smem + OFF_SQJ);

    int tid = threadIdx.x, wid = tid >> 5, lane = tid & 31;
    int wr = wid >> 1, wc = wid & 1;   // warp tile: rows wr*32, cols wc*64

    // stage both fp16 tiles via cp.async (row = 256B = 16 chunks)
    {
        const char* srcA = (const char*)(g_h + (size_t)I * D);
        const char* srcB = (const char*)(g_h + (size_t)J * D);
        #pragma unroll
        for (int t = tid; t < 2048; t += 256) {
            int r = t >> 4, c = t & 15;
            cp_async16(sbase + (uint32_t)(r * PITCHB + c * 16),
                       srcA + (size_t)r * 256 + c * 16);
            cp_async16(sbase + TILEB + (uint32_t)(r * PITCHB + c * 16),
                       srcB + (size_t)r * 256 + c * 16);
        }
        asm volatile("cp.async.commit_group;" ::: "memory");
    }
    if (tid < 128) sqi[tid] = g_sqh[I + tid];
    else sqj[tid - 128] = g_sqh[J + tid - 128];
    asm volatile("cp.async.wait_group 0;" ::: "memory");
    __syncthreads();

    float acc[2][8][4];
    #pragma unroll
    for (int mi = 0; mi < 2; mi++)
        #pragma unroll
        for (int ni = 0; ni < 8; ni++)
            #pragma unroll
            for (int q = 0; q < 4; q++) acc[mi][ni][q] = 0.f;

    uint32_t aAddr0 = sbase + (uint32_t)((wr * 32 + (lane & 15)) * PITCHB +
                                         (lane >> 4) * 16);
    uint32_t bAddr0 = sbase + TILEB +
                      (uint32_t)((wc * 64 + (lane & 15)) * PITCHB +
                                 (lane >> 4) * 16);

    #pragma unroll
    for (int ks = 0; ks < 8; ks++) {
        uint32_t a[2][4];
        ldm_x4(a[0], aAddr0 + ks * 32);
        ldm_x4(a[1], aAddr0 + ks * 32 + 16 * PITCHB);
        uint32_t b[4][4];
        #pragma unroll
        for (int n2 = 0; n2 < 4; n2++)
            ldm_x4(b[n2], bAddr0 + ks * 32 + n2 * 16 * PITCHB);
        #pragma unroll
        for (int mi = 0; mi < 2; mi++)
            #pragma unroll
            for (int ni = 0; ni < 8; ni++)
                mma_f16(acc[mi][ni], a[mi],
                        b[ni >> 1][ni & 1], b[ni >> 1][(ni & 1) + 2]);
    }
    __syncthreads();   // operands dead; reuse smem for dist tile

    // dot -> dist, dist tile to smem
    #pragma unroll
    for (int mi = 0; mi < 2; mi++) {
        int rbase = wr * 32 + mi * 16 + (lane >> 2);
        #pragma unroll
        for (int ni = 0; ni < 8; ni++) {
            int cbase = wc * 64 + ni * 8 + (lane & 3) * 2;
            #pragma unroll
            for (int q = 0; q < 4; q++) {
                int r = rbase + (q >> 1) * 8;
                int c = cbase + (q & 1);
                float d2 = sqi[r] + sqj[c] - 2.f * acc[mi][ni][q];
                float dv = sqrtf(fmaxf(d2, 0.f));
                if (diag && r == c) dv = 0.f;
                sdist[r * PT + c] = dv;
            }
        }
    }
    __syncthreads();

    // pass A: rows I+r vs mask[I+r][J..]
    #pragma unroll 1
    for (int rr = 0; rr < 16; rr++) {
        int r = wid * 16 + rr;
        const float* mrow = mask + (size_t)(I + r) * N + J;
        float ps = 0.f, ct = 0.f;
        #pragma unroll
        for (int q = 0; q < 4; q++) {
            float m = mrow[q * 32 + lane];
            ps += m * sdist[r * PT + q * 32 + lane];
            ct += m;
        }
        #pragma unroll
        for (int o = 16; o > 0; o >>= 1) {
            ps += __shfl_down_sync(0xffffffffu, ps, o);
            ct += __shfl_down_sync(0xffffffffu, ct, o);
        }
        if (lane == 0)
            atomicAdd(&g_acc[I + r], (double)ps + (double)ct * PACK);
    }

    // pass B (off-diag): rows J+c vs mask[J+c][I..]
    if (!diag) {
        #pragma unroll 1
        for (int cc = 0; cc < 16; cc++) {
            int c = wid * 16 + cc;
            const float* mrow = mask + (size_t)(J + c) * N + I;
            float ps = 0.f, ct = 0.f;
            #pragma unroll
            for (int q = 0; q < 4; q++) {
                float m = mrow[q * 32 + lane];
                ps += m * sdist[(q * 32 + lane) * PT + c];
                ct += m;
            }
            #pragma unroll
            for (int o = 16; o > 0; o >>= 1) {
                ps += __shfl_down_sync(0xffffffffu, ps, o);
                ct += __shfl_down_sync(0xffffffffu, ct, o);
            }
            if (lane == 0)
                atomicAdd(&g_acc[J + c], (double)ps + (double)ct * PACK);
        }
    }
}

// ---------------------------------------------------------------------------
// Kernel 3: unpack (ps, ct) and reduce to the scalar mean
// ---------------------------------------------------------------------------
__global__ void k_final(float* __restrict__ out, int N) {
    __shared__ float sb[32];
    float s = 0.f;
    for (int i = threadIdx.x; i < N; i += blockDim.x) {
        double v = g_acc[i];
        double ct = floor(v / PACK);
        double ps = v - ct * PACK;
        s += (float)(ps / fmax(ct, 1.0)) - g_negdist[i];
    }
    #pragma unroll
    for (int o = 16; o > 0; o >>= 1) s += __shfl_down_sync(0xffffffffu, s, o);
    int lane = threadIdx.x & 31, w = threadIdx.x >> 5;
    if (lane == 0) sb[w] = s;
    __syncthreads();
    if (w == 0) {
        float r = (lane < (int)(blockDim.x >> 5)) ? sb[lane] : 0.f;
        #pragma unroll
        for (int o = 16; o > 0; o >>= 1) r += __shfl_down_sync(0xffffffffu, r, o);
        if (lane == 0) out[0] = r / (float)N;
    }
}

// ---------------------------------------------------------------------------
extern "C" void kernel_launch(void* const* d_in, const int* in_sizes, int n_in,
                              void* d_out, int out_size) {
    const float* pred = (const float*)d_in[0];
    const float* mask = (const float*)d_in[1];
    const float* neg  = (const float*)d_in[2];
    int N = in_sizes[0] / D;

    k_normalize<<<N / 8, 256>>>(pred, neg, N);

    int nb = N / BM;
    cudaFuncSetAttribute(k_gram, cudaFuncAttributeMaxDynamicSharedMemorySize,
                         SMEM_SZ);
    dim3 grid(nb, nb);
    k_gram<<<grid, 256, SMEM_SZ>>>(mask, N);

    k_final<<<1, 1024>>>((float*)d_out, N);
}

// round 7
// speedup vs baseline: 1.7659x; 1.2016x over previous
#include <cuda_runtime.h>
#include <cuda_fp16.h>
#include <math.h>
#include <stdint.h>

#define D      128
#define MAXN   8192
#define BM     128
#define PITCHB 272              // smem tile pitch bytes (136 halves)
#define TILEB  (128 * PITCHB)   // 34816
#define PT     129              // dist tile pitch (floats)
#define PACK   16777216.0       // 2^24 for (ps, ct) double packing

__device__ __half  g_h[(size_t)MAXN * D];
__device__ float   g_sqh[MAXN];
__device__ float   g_negdist[MAXN];
__device__ double  g_acc[MAXN];

// ---------------- helpers ----------------
__device__ __forceinline__ uint32_t smem_u32(const void* p) {
    uint32_t a;
    asm("{ .reg .u64 t; cvta.to.shared.u64 t, %1; cvt.u32.u64 %0, t; }"
        : "=r"(a) : "l"(p));
    return a;
}
__device__ __forceinline__ void cp_async16(uint32_t dst, const void* src) {
    size_t g = __cvta_generic_to_global(src);
    asm volatile("cp.async.cg.shared.global [%0], [%1], 16;"
                 :: "r"(dst), "l"(g) : "memory");
}
__device__ __forceinline__ void ldm_x4(uint32_t* r, uint32_t addr) {
    asm volatile("ldmatrix.sync.aligned.m8n8.x4.shared.b16 {%0,%1,%2,%3}, [%4];"
                 : "=r"(r[0]), "=r"(r[1]), "=r"(r[2]), "=r"(r[3]) : "r"(addr));
}
__device__ __forceinline__ void mma_f16(float* c, const uint32_t* a,
                                        uint32_t b0, uint32_t b1) {
    asm volatile(
        "mma.sync.aligned.m16n8k16.row.col.f32.f16.f16.f32 "
        "{%0,%1,%2,%3}, {%4,%5,%6,%7}, {%8,%9}, {%0,%1,%2,%3};"
        : "+f"(c[0]), "+f"(c[1]), "+f"(c[2]), "+f"(c[3])
        : "r"(a[0]), "r"(a[1]), "r"(a[2]), "r"(a[3]), "r"(b0), "r"(b1));
}

// ---------------------------------------------------------------------------
// Kernel 0: zero accumulators (also shifts ncu capture alignment)
// ---------------------------------------------------------------------------
__global__ void k_zero(int N) {
    int i = blockIdx.x * blockDim.x + threadIdx.x;
    if (i < N) g_acc[i] = 0.0;
}

// ---------------------------------------------------------------------------
// Kernel 1: warp-per-row normalize; fp16 rows, sq of ROUNDED rows, neg_dist.
// ---------------------------------------------------------------------------
__global__ __launch_bounds__(256) void k_normalize(const float* __restrict__ pred,
                                                   const float* __restrict__ neg,
                                                   int N) {
    int w = threadIdx.x >> 5, lane = threadIdx.x & 31;
    int row = blockIdx.x * 8 + w;
    float4 pv = ((const float4*)pred)[(size_t)row * 32 + lane];
    float4 nv = ((const float4*)neg)[(size_t)row * 32 + lane];
    float s1 = pv.x * pv.x + pv.y * pv.y + pv.z * pv.z + pv.w * pv.w;
    float s2 = nv.x * nv.x + nv.y * nv.y + nv.z * nv.z + nv.w * nv.w;
    #pragma unroll
    for (int o = 16; o > 0; o >>= 1) {
        s1 += __shfl_xor_sync(0xffffffffu, s1, o);
        s2 += __shfl_xor_sync(0xffffffffu, s2, o);
    }
    float r1 = fmaxf(sqrtf(s1), 1e-12f);
    float r2 = fmaxf(sqrtf(s2), 1e-12f);
    float4 pn = make_float4(pv.x / r1, pv.y / r1, pv.z / r1, pv.w / r1);
    float4 nn = make_float4(nv.x / r2, nv.y / r2, nv.z / r2, nv.w / r2);

    __half h0 = __float2half(pn.x), h1 = __float2half(pn.y);
    __half h2 = __float2half(pn.z), h3 = __float2half(pn.w);
    float f0 = __half2float(h0), f1 = __half2float(h1);
    float f2 = __half2float(h2), f3 = __half2float(h3);
    float s3 = f0 * f0 + f1 * f1 + f2 * f2 + f3 * f3;   // sq of rounded
    float dx = pn.x - nn.x, dy = pn.y - nn.y, dz = pn.z - nn.z, dw = pn.w - nn.w;
    float s4 = dx * dx + dy * dy + dz * dz + dw * dw;
    #pragma unroll
    for (int o = 16; o > 0; o >>= 1) {
        s3 += __shfl_xor_sync(0xffffffffu, s3, o);
        s4 += __shfl_xor_sync(0xffffffffu, s4, o);
    }
    __half2* dst = (__half2*)(g_h + (size_t)row * D) + lane * 2;
    dst[0] = __halves2half2(h0, h1);
    dst[1] = __halves2half2(h2, h3);
    if (lane == 0) {
        g_sqh[row]     = s3;
        g_negdist[row] = (s4 > 0.f) ? sqrtf(s4) : 0.f;
    }
}

// ---------------------------------------------------------------------------
// Kernel 2: 128x128 gram tiles, 1D triangular grid, single fp16 mma pass,
// fused A+B epilogue rows (batched loads), forced occupancy 2.
// ---------------------------------------------------------------------------
#define OFF_SQI (2 * TILEB)
#define OFF_SQJ (2 * TILEB + 512)
#define SMEM_SZ (2 * TILEB + 1024)

__global__ __launch_bounds__(256, 2) void k_gram(const float* __restrict__ mask,
                                                 int N, int nb) {
    // triangular decode: t -> (bi, bj), bj >= bi
    int t = blockIdx.x;
    float ff = (float)(2 * nb + 1);
    int bi = (int)((ff - sqrtf(ff * ff - 8.0f * (float)t)) * 0.5f);
    #pragma unroll 1
    while (bi > 0 && (bi * nb - (bi * (bi - 1)) / 2) > t) bi--;
    #pragma unroll 1
    while (((bi + 1) * nb - ((bi + 1) * bi) / 2) <= t) bi++;
    int bj = bi + (t - (bi * nb - (bi * (bi - 1)) / 2));
    bool diag = (bi == bj);
    int I = bi * BM, J = bj * BM;

    extern __shared__ char smem[];
    uint32_t sbase = smem_u32(smem);
    float* sdist = (float*)smem;
    float* sqi = (float*)(smem + OFF_SQI);
    float* sqj = (float*)(smem + OFF_SQJ);

    int tid = threadIdx.x, wid = tid >> 5, lane = tid & 31;
    int wr = wid >> 1, wc = wid & 1;   // warp tile: rows wr*32, cols wc*64

    // stage both fp16 tiles via cp.async
    {
        const char* srcA = (const char*)(g_h + (size_t)I * D);
        const char* srcB = (const char*)(g_h + (size_t)J * D);
        #pragma unroll
        for (int t2 = tid; t2 < 2048; t2 += 256) {
            int r = t2 >> 4, c = t2 & 15;
            cp_async16(sbase + (uint32_t)(r * PITCHB + c * 16),
                       srcA + (size_t)r * 256 + c * 16);
            cp_async16(sbase + TILEB + (uint32_t)(r * PITCHB + c * 16),
                       srcB + (size_t)r * 256 + c * 16);
        }
        asm volatile("cp.async.commit_group;" ::: "memory");
    }
    if (tid < 128) sqi[tid] = g_sqh[I + tid];
    else sqj[tid - 128] = g_sqh[J + tid - 128];
    asm volatile("cp.async.wait_group 0;" ::: "memory");
    __syncthreads();

    float acc[2][8][4];
    #pragma unroll
    for (int mi = 0; mi < 2; mi++)
        #pragma unroll
        for (int ni = 0; ni < 8; ni++)
            #pragma unroll
            for (int q = 0; q < 4; q++) acc[mi][ni][q] = 0.f;

    uint32_t aAddr0 = sbase + (uint32_t)((wr * 32 + (lane & 15)) * PITCHB +
                                         (lane >> 4) * 16);
    uint32_t bAddr0 = sbase + TILEB +
                      (uint32_t)((wc * 64 + (lane & 15)) * PITCHB +
                                 (lane >> 4) * 16);

    #pragma unroll
    for (int ks = 0; ks < 8; ks++) {
        uint32_t a[2][4];
        ldm_x4(a[0], aAddr0 + ks * 32);
        ldm_x4(a[1], aAddr0 + ks * 32 + 16 * PITCHB);
        uint32_t b[4][4];
        #pragma unroll
        for (int n2 = 0; n2 < 4; n2++)
            ldm_x4(b[n2], bAddr0 + ks * 32 + n2 * 16 * PITCHB);
        #pragma unroll
        for (int mi = 0; mi < 2; mi++)
            #pragma unroll
            for (int ni = 0; ni < 8; ni++)
                mma_f16(acc[mi][ni], a[mi],
                        b[ni >> 1][ni & 1], b[ni >> 1][(ni & 1) + 2]);
    }
    __syncthreads();   // operands dead; reuse smem for dist tile

    // dot -> dist, dist tile to smem
    #pragma unroll
    for (int mi = 0; mi < 2; mi++) {
        int rbase = wr * 32 + mi * 16 + (lane >> 2);
        #pragma unroll
        for (int ni = 0; ni < 8; ni++) {
            int cbase = wc * 64 + ni * 8 + (lane & 3) * 2;
            #pragma unroll
            for (int q = 0; q < 4; q++) {
                int r = rbase + (q >> 1) * 8;
                int c = cbase + (q & 1);
                float d2 = sqi[r] + sqj[c] - 2.f * acc[mi][ni][q];
                float dv = sqrtf(fmaxf(d2, 0.f));
                if (diag && r == c) dv = 0.f;
                sdist[r * PT + c] = dv;
            }
        }
    }
    __syncthreads();

    // fused epilogue: each iteration handles one A-row and one B-row
    // (8 batched LDGs, two interleaved reduction trees)
    #pragma unroll 2
    for (int rr = 0; rr < 16; rr++) {
        int r = wid * 16 + rr;
        const float* mrowA = mask + (size_t)(I + r) * N + J;
        const float* mrowB = mask + (size_t)(J + r) * N + I;
        float mA[4], mB[4];
        #pragma unroll
        for (int q = 0; q < 4; q++) mA[q] = mrowA[q * 32 + lane];
        if (!diag) {
            #pragma unroll
            for (int q = 0; q < 4; q++) mB[q] = mrowB[q * 32 + lane];
        }
        float psA = 0.f, ctA = 0.f, psB = 0.f, ctB = 0.f;
        #pragma unroll
        for (int q = 0; q < 4; q++) {
            psA += mA[q] * sdist[r * PT + q * 32 + lane];
            ctA += mA[q];
        }
        if (!diag) {
            #pragma unroll
            for (int q = 0; q < 4; q++) {
                psB += mB[q] * sdist[(q * 32 + lane) * PT + r];
                ctB += mB[q];
            }
        }
        #pragma unroll
        for (int o = 16; o > 0; o >>= 1) {
            psA += __shfl_down_sync(0xffffffffu, psA, o);
            ctA += __shfl_down_sync(0xffffffffu, ctA, o);
            psB += __shfl_down_sync(0xffffffffu, psB, o);
            ctB += __shfl_down_sync(0xffffffffu, ctB, o);
        }
        if (lane == 0) {
            atomicAdd(&g_acc[I + r], (double)psA + (double)ctA * PACK);
            if (!diag)
                atomicAdd(&g_acc[J + r], (double)psB + (double)ctB * PACK);
        }
    }
}

// ---------------------------------------------------------------------------
// Kernel 3: unpack (ps, ct) and reduce to the scalar mean
// ---------------------------------------------------------------------------
__global__ void k_final(float* __restrict__ out, int N) {
    __shared__ float sb[32];
    float s = 0.f;
    for (int i = threadIdx.x; i < N; i += blockDim.x) {
        double v = g_acc[i];
        double ct = floor(v / PACK);
        double ps = v - ct * PACK;
        s += (float)(ps / fmax(ct, 1.0)) - g_negdist[i];
    }
    #pragma unroll
    for (int o = 16; o > 0; o >>= 1) s += __shfl_down_sync(0xffffffffu, s, o);
    int lane = threadIdx.x & 31, w = threadIdx.x >> 5;
    if (lane == 0) sb[w] = s;
    __syncthreads();
    if (w == 0) {
        float r = (lane < (int)(blockDim.x >> 5)) ? sb[lane] : 0.f;
        #pragma unroll
        for (int o = 16; o > 0; o >>= 1) r += __shfl_down_sync(0xffffffffu, r, o);
        if (lane == 0) out[0] = r / (float)N;
    }
}

// ---------------------------------------------------------------------------
extern "C" void kernel_launch(void* const* d_in, const int* in_sizes, int n_in,
                              void* d_out, int out_size) {
    const float* pred = (const float*)d_in[0];
    const float* mask = (const float*)d_in[1];
    const float* neg  = (const float*)d_in[2];
    int N = in_sizes[0] / D;

    k_zero<<<(N + 255) / 256, 256>>>(N);
    k_normalize<<<N / 8, 256>>>(pred, neg, N);

    int nb = N / BM;
    int ntiles = nb * (nb + 1) / 2;
    cudaFuncSetAttribute(k_gram, cudaFuncAttributeMaxDynamicSharedMemorySize,
                         SMEM_SZ);
    k_gram<<<ntiles, 256, SMEM_SZ>>>(mask, N, nb);

    k_final<<<1, 1024>>>((float*)d_out, N);
}